// round 14
// baseline (speedup 1.0000x reference)
#include <cuda_runtime.h>
#include <cuda_bf16.h>
#include <math.h>
#include <stdint.h>

#define BB 2
#define NN 64
#define EE 256
#define HH 8
#define DD 32
#define FF 512
#define MR 8192
#define LNEPS 1e-5f

// ---------------- scratch ----------------
__device__ float g_q [MR*EE];
__device__ float g_k [MR*EE];
__device__ float g_v1[MR*EE];
__device__ float g_v2[MR*EE];
__device__ float g_h [MR*EE];
__device__ __nv_bfloat16 g_x2 [MR*512];
__device__ __nv_bfloat16 g_ao2[MR*512];
__device__ __nv_bfloat16 g_h2 [MR*512];
__device__ __nv_bfloat16 g_m12[(size_t)MR*1024];
__device__ __nv_bfloat16 g_wqkv2[1024*512];
__device__ __nv_bfloat16 g_wot2 [256*512];
__device__ __nv_bfloat16 g_w1t2 [512*512];
__device__ __nv_bfloat16 g_w2t2 [256*1024];

// ---------------- helpers ----------------
__device__ __forceinline__ uint32_t s2u(const void* p) {
    uint32_t a;
    asm("{ .reg .u64 t; cvta.to.shared.u64 t, %1; cvt.u32.u64 %0, t; }" : "=r"(a) : "l"(p));
    return a;
}
__device__ __forceinline__ void ldsm4(uint32_t* r, uint32_t a) {
    asm volatile("ldmatrix.sync.aligned.m8n8.x4.shared.b16 {%0,%1,%2,%3}, [%4];"
        : "=r"(r[0]), "=r"(r[1]), "=r"(r[2]), "=r"(r[3]) : "r"(a));
}
__device__ __forceinline__ void mma16816(float* c, const uint32_t* a, const uint32_t* b) {
    asm volatile("mma.sync.aligned.m16n8k16.row.col.f32.bf16.bf16.f32 "
        "{%0,%1,%2,%3}, {%4,%5,%6,%7}, {%8,%9}, {%0,%1,%2,%3};"
        : "+f"(c[0]), "+f"(c[1]), "+f"(c[2]), "+f"(c[3])
        : "r"(a[0]), "r"(a[1]), "r"(a[2]), "r"(a[3]), "r"(b[0]), "r"(b[1]));
}
__device__ __forceinline__ void bfsplit(float v, __nv_bfloat16& h, __nv_bfloat16& l) {
    h = __float2bfloat16_rn(v);
    l = __float2bfloat16_rn(v - __bfloat162float(h));
}
__device__ __forceinline__ void fma2(float2& c, const float2 a, const float2 b) {
    asm("fma.rn.f32x2 %0, %1, %2, %0;"
        : "+l"(reinterpret_cast<unsigned long long&>(c))
        : "l"(reinterpret_cast<const unsigned long long&>(a)),
          "l"(reinterpret_cast<const unsigned long long&>(b)));
}
__device__ __forceinline__ void mul2(float2& c, const float2 a, const float2 b) {
    asm("mul.rn.f32x2 %0, %1, %2;"
        : "=l"(reinterpret_cast<unsigned long long&>(c))
        : "l"(reinterpret_cast<const unsigned long long&>(a)),
          "l"(reinterpret_cast<const unsigned long long&>(b)));
}
__device__ __forceinline__ float2 dup2(float x) { float2 r; r.x = x; r.y = x; return r; }
__device__ __forceinline__ void cpasync16(uint32_t dst, const void* src) {
    asm volatile("cp.async.cg.shared.global [%0], [%1], 16;" :: "r"(dst), "l"(src) : "memory");
}
#define CP_COMMIT asm volatile("cp.async.commit_group;" ::: "memory")
#define CP_WAIT2  asm volatile("cp.async.wait_group 2;" ::: "memory")
#define CP_WAIT1  asm volatile("cp.async.wait_group 1;" ::: "memory")
#define CP_WAIT0  asm volatile("cp.async.wait_group 0;" ::: "memory")

__global__ void nop_k() {}

// =====================================================================
// prep_all (unchanged, passing)
// =====================================================================
__global__ void __launch_bounds__(256)
prep_all(const float* __restrict__ x,
         const float* __restrict__ Wq, const float* __restrict__ Wk,
         const float* __restrict__ Wv1, const float* __restrict__ Wv2,
         const float* __restrict__ Wo, const float* __restrict__ W1,
         const float* __restrict__ W2)
{
    const int blk = blockIdx.x, tid = threadIdx.x;
    if (blk < 512) {
        const int base = blk * 4096;
        #pragma unroll
        for (int i = 0; i < 16; i++) {
            int t = base + i * 256 + tid;
            int row = t >> 8, c = t & 255;
            float v = x[t];
            __nv_bfloat16 h, l; bfsplit(v, h, l);
            g_x2[(size_t)row * 512 + c] = h;
            g_x2[(size_t)row * 512 + 256 + c] = l;
        }
        return;
    }
    __shared__ float tile[32][33];
    const int wb = blk - 512;
    const float* W; __nv_bfloat16* out; int K, N, tr, tc;
    if (wb < 256) {
        const int w = wb >> 6, t6 = wb & 63;
        W = (w == 0) ? Wq : (w == 1) ? Wk : (w == 2) ? Wv1 : Wv2;
        out = g_wqkv2 + w * 256 * 512; K = 256; N = 256; tr = t6 >> 3; tc = t6 & 7;
    } else if (wb < 320) {
        const int t6 = wb - 256;
        W = Wo; out = g_wot2; K = 256; N = 256; tr = t6 >> 3; tc = t6 & 7;
    } else if (wb < 448) {
        const int t6 = wb - 320;
        W = W1; out = g_w1t2; K = 256; N = 512; tr = t6 >> 4; tc = t6 & 15;
    } else {
        const int t6 = wb - 448;
        W = W2; out = g_w2t2; K = 512; N = 256; tr = t6 >> 3; tc = t6 & 7;
    }
    const int k0 = tr * 32, n0 = tc * 32;
    const int r = tid >> 3, c4 = (tid & 7) * 4;
    #pragma unroll
    for (int i = 0; i < 4; i++)
        tile[r][c4 + i] = W[(size_t)(k0 + r) * N + n0 + c4 + i];
    __syncthreads();
    #pragma unroll
    for (int i = 0; i < 4; i++) {
        float v = tile[c4 + i][r];
        __nv_bfloat16 h, l; bfsplit(v, h, l);
        out[(size_t)(n0 + r) * 2 * K + k0 + c4 + i] = h;
        out[(size_t)(n0 + r) * 2 * K + K + k0 + c4 + i] = l;
    }
}

// =====================================================================
// bf16 split-precision mma.sync GEMM v2:
// 4-stage cp.async ring, K-chunk = 16 (one k16), ONE sync per chunk,
// prefetch distance 3. Stage rows padded to 24 elems (48B) -> ldsm
// banks {0,12,24,4,16,28,8,20} conflict-free.
// =====================================================================
template<int BM, int BN, int KDIM, int MODE, int MINB>
__global__ void __launch_bounds__(256, MINB)
gemm_mma(const __nv_bfloat16* __restrict__ A2, const __nv_bfloat16* __restrict__ B2,
         const float* __restrict__ res, const float* __restrict__ bias,
         const float* __restrict__ lg, const float* __restrict__ lb,
         float* __restrict__ o0, void* __restrict__ o1v,
         float* __restrict__ o2, float* __restrict__ o3)
{
    constexpr int K2 = 2 * KDIM, C = KDIM / 16;
    constexpr int WR = BM / 32;
    constexpr int RS = 24;                       // padded row stride (elems)
    constexpr int AH = 0, AL = BM * RS, BH = 2 * BM * RS, BL = 2 * BM * RS + BN * RS;
    constexpr int SB = 2 * BM * RS + 2 * BN * RS; // elems per stage
    extern __shared__ __nv_bfloat16 sm[];
    const int tid = threadIdx.x, wid = tid >> 5, lane = tid & 31;
    const int mBase = blockIdx.x * BM, nBase = blockIdx.y * BN;
    const int wrB = (wid % WR) * 32, wcB = (wid / WR) * 64;
    const uint32_t smu = s2u(sm);

    float acc[2][8][4];
    #pragma unroll
    for (int i = 0; i < 2; i++)
        #pragma unroll
        for (int j = 0; j < 8; j++)
            #pragma unroll
            for (int v = 0; v < 4; v++) acc[i][j][v] = 0.f;

    const int aRow = lane & 15, aK = ((lane >> 4) & 1) * 8;
    const int bN = ((lane >> 4) & 1) * 8 + (lane & 7), bK = ((lane >> 3) & 1) * 8;

    auto issue = [&](int c, int s) {
        const int ca = c * 16;
        const uint32_t base = smu + 2u * (uint32_t)(s * SB);
        #pragma unroll
        for (int f = tid; f < BM * 2; f += 256) {
            int r = f >> 1, c8 = (f & 1) * 8;
            const __nv_bfloat16* src = &A2[(size_t)(mBase + r) * K2 + ca + c8];
            cpasync16(base + 2u * (AH + r * RS + c8), src);
            cpasync16(base + 2u * (AL + r * RS + c8), src + KDIM);
        }
        #pragma unroll
        for (int f = tid; f < BN * 2; f += 256) {
            int r = f >> 1, c8 = (f & 1) * 8;
            const __nv_bfloat16* src = &B2[(size_t)(nBase + r) * K2 + ca + c8];
            cpasync16(base + 2u * (BH + r * RS + c8), src);
            cpasync16(base + 2u * (BL + r * RS + c8), src + KDIM);
        }
    };

    issue(0, 0); CP_COMMIT;
    issue(1, 1); CP_COMMIT;
    issue(2, 2); CP_COMMIT;
    for (int c = 0; c < C; c++) {
        // await own group c (tail: fewer pending, step wait down)
        if (c < C - 2)      CP_WAIT2;
        else if (c == C - 2) CP_WAIT1;
        else                 CP_WAIT0;
        __syncthreads();     // all threads' group-c copies visible; readers of c-1 done
        if (c + 3 < C) { issue(c + 3, (c + 3) & 3); CP_COMMIT; }
        const uint32_t sb = smu + 2u * (uint32_t)((c & 3) * SB);

        uint32_t ah[2][4], al_[2][4], bh[8][2], bl_[8][2];
        #pragma unroll
        for (int mr = 0; mr < 2; mr++) {
            ldsm4(ah[mr],  sb + 2u * (AH + (wrB + mr * 16 + aRow) * RS + aK));
            ldsm4(al_[mr], sb + 2u * (AL + (wrB + mr * 16 + aRow) * RS + aK));
        }
        #pragma unroll
        for (int np = 0; np < 4; np++) {
            uint32_t r4[4];
            ldsm4(r4, sb + 2u * (BH + (wcB + np * 16 + bN) * RS + bK));
            bh[2*np][0] = r4[0]; bh[2*np][1] = r4[1];
            bh[2*np+1][0] = r4[2]; bh[2*np+1][1] = r4[3];
            ldsm4(r4, sb + 2u * (BL + (wcB + np * 16 + bN) * RS + bK));
            bl_[2*np][0] = r4[0]; bl_[2*np][1] = r4[1];
            bl_[2*np+1][0] = r4[2]; bl_[2*np+1][1] = r4[3];
        }
        #pragma unroll
        for (int mr = 0; mr < 2; mr++)
            #pragma unroll
            for (int nc = 0; nc < 8; nc++) mma16816(acc[mr][nc], ah[mr], bh[nc]);
        #pragma unroll
        for (int mr = 0; mr < 2; mr++)
            #pragma unroll
            for (int nc = 0; nc < 8; nc++) mma16816(acc[mr][nc], ah[mr], bl_[nc]);
        #pragma unroll
        for (int mr = 0; mr < 2; mr++)
            #pragma unroll
            for (int nc = 0; nc < 8; nc++) mma16816(acc[mr][nc], al_[mr], bh[nc]);
    }
    __syncthreads();

    const int lR = lane >> 2, lC = (lane & 3) * 2;
    if constexpr (MODE == 0) {
        const int sel = blockIdx.y >> 1;
        float* qout = sel == 0 ? o0 : sel == 1 ? (float*)o1v : sel == 2 ? o2 : o3;
        const int colBase = (blockIdx.y & 1) * 128 + wcB;
        #pragma unroll
        for (int mr = 0; mr < 2; mr++)
            #pragma unroll
            for (int nc = 0; nc < 8; nc++) {
                int row = mBase + wrB + mr * 16 + lR;
                int col = colBase + nc * 8 + lC;
                *(float2*)&qout[(size_t)row * 256 + col] = make_float2(acc[mr][nc][0], acc[mr][nc][1]);
                *(float2*)&qout[(size_t)(row + 8) * 256 + col] = make_float2(acc[mr][nc][2], acc[mr][nc][3]);
            }
    } else if constexpr (MODE == 1) {
        __nv_bfloat16* out = (__nv_bfloat16*)o1v;
        #pragma unroll
        for (int mr = 0; mr < 2; mr++)
            #pragma unroll
            for (int nc = 0; nc < 8; nc++) {
                int row = mBase + wrB + mr * 16 + lR;
                int colG = nBase + wcB + nc * 8 + lC;
                float b0 = bias[colG], b1 = bias[colG + 1];
                #pragma unroll
                for (int s = 0; s < 2; s++) {
                    int rr = row + s * 8;
                    float v0 = fmaxf(acc[mr][nc][2*s] + b0, 0.f);
                    float v1 = fmaxf(acc[mr][nc][2*s+1] + b1, 0.f);
                    __nv_bfloat162 hv, lv;
                    bfsplit(v0, hv.x, lv.x); bfsplit(v1, hv.y, lv.y);
                    *(__nv_bfloat162*)&out[(size_t)rr * 1024 + colG] = hv;
                    *(__nv_bfloat162*)&out[(size_t)rr * 1024 + 512 + colG] = lv;
                }
            }
    } else {
        float* stage = (float*)sm;   // [64][264]
        #pragma unroll
        for (int mr = 0; mr < 2; mr++)
            #pragma unroll
            for (int nc = 0; nc < 8; nc++) {
                int rowL = wrB + mr * 16 + lR;
                int col = wcB + nc * 8 + lC;
                *(float2*)&stage[rowL * 264 + col] = make_float2(acc[mr][nc][0], acc[mr][nc][1]);
                *(float2*)&stage[(rowL + 8) * 264 + col] = make_float2(acc[mr][nc][2], acc[mr][nc][3]);
            }
        __syncthreads();
        const int r = tid >> 2, q = tid & 3;
        const size_t grow = mBase + r;
        float sum = 0.f, sq = 0.f;
        #pragma unroll
        for (int c4 = 0; c4 < 16; c4++) {
            int cc = q * 64 + c4 * 4;
            float4 v = *(float4*)&stage[r * 264 + cc];
            float4 rv = *(const float4*)&res[grow * 256 + cc];
            v.x += rv.x; v.y += rv.y; v.z += rv.z; v.w += rv.w;
            if constexpr (MODE == 3) {
                float4 bv = *(const float4*)&bias[cc];
                v.x += bv.x; v.y += bv.y; v.z += bv.z; v.w += bv.w;
            }
            *(float4*)&stage[r * 264 + cc] = v;
            sum += v.x + v.y + v.z + v.w;
            sq  += v.x * v.x + v.y * v.y + v.z * v.z + v.w * v.w;
        }
        sum += __shfl_xor_sync(0xffffffffu, sum, 1);
        sum += __shfl_xor_sync(0xffffffffu, sum, 2);
        sq  += __shfl_xor_sync(0xffffffffu, sq, 1);
        sq  += __shfl_xor_sync(0xffffffffu, sq, 2);
        const float mean = sum * (1.f / 256.f);
        const float var  = sq * (1.f / 256.f) - mean * mean;
        const float rs   = rsqrtf(var + LNEPS);
        __nv_bfloat16* h2o = (__nv_bfloat16*)o1v;
        #pragma unroll
        for (int c4 = 0; c4 < 16; c4++) {
            int cc = q * 64 + c4 * 4;
            float4 v = *(float4*)&stage[r * 264 + cc];
            float4 g4 = *(const float4*)&lg[cc];
            float4 b4 = *(const float4*)&lb[cc];
            float4 y;
            y.x = (v.x - mean) * rs * g4.x + b4.x;
            y.y = (v.y - mean) * rs * g4.y + b4.y;
            y.z = (v.z - mean) * rs * g4.z + b4.z;
            y.w = (v.w - mean) * rs * g4.w + b4.w;
            *(float4*)&o0[grow * 256 + cc] = y;
            if constexpr (MODE == 2) {
                __nv_bfloat162 h01, l01, h23, l23;
                bfsplit(y.x, h01.x, l01.x); bfsplit(y.y, h01.y, l01.y);
                bfsplit(y.z, h23.x, l23.x); bfsplit(y.w, h23.y, l23.y);
                *(__nv_bfloat162*)&h2o[grow * 512 + cc]       = h01;
                *(__nv_bfloat162*)&h2o[grow * 512 + cc + 2]   = h23;
                *(__nv_bfloat162*)&h2o[grow * 512 + 256 + cc]     = l01;
                *(__nv_bfloat162*)&h2o[grow * 512 + 256 + cc + 2] = l23;
            }
        }
    }
}

// =====================================================================
// Fused attention v5 (unchanged from R13, passing)
// =====================================================================
#define SM_S   0
#define SM_QV  32768
#define SM_ST  49152
#define KTSLOT 2112
#define VSLOT  2560
#define KTSTRIDE 66
#define VTSTRIDE 40
#define ATTN_SMEM ((49152 + 4 * 2112) * 4)

__global__ void __launch_bounds__(512, 1)
attn_fused() {
    extern __shared__ float smf[];
    float* S  = smf + SM_S;
    float* QV = smf + SM_QV;
    float* ST = smf + SM_ST;
    const int bid = blockIdx.x;
    const int it = bid & 7, h = (bid >> 3) & 7, b = bid >> 6;
    const int iBase = it * 8;
    const int tid = threadIdx.x, wid = tid >> 5, lane = tid & 31;
    const float SC = 0.17677669529663687f;
    const uint32_t st_u = s2u(ST);

    const int sj0 = tid >> 3, sc0 = (tid & 7) * 4;
    auto ldT = [&](const float* __restrict__ src, int l, float4& r0) {
        r0 = *(const float4*)&src[((size_t)((b * NN + l) * NN + sj0)) * EE + h * DD + sc0];
    };
    auto stT = [&](float* kt, float4 r0) {
        kt[(sc0+0)*KTSTRIDE + sj0] = r0.x; kt[(sc0+1)*KTSTRIDE + sj0] = r0.y;
        kt[(sc0+2)*KTSTRIDE + sj0] = r0.z; kt[(sc0+3)*KTSTRIDE + sj0] = r0.w;
    };
    auto ldQV = [&](const float* __restrict__ src) {
        #pragma unroll
        for (int k = 0; k < 8; k++) {
            int f = tid + 512 * k;
            int row = f >> 3, d4 = (f & 7) * 4;
            int l = row >> 3, ip = row & 7;
            float4 v = *(const float4*)&src[((size_t)((b*NN + iBase + ip)*NN + l))*EE + h*DD + d4];
            *(float4*)&QV[row * 32 + d4] = v;
        }
    };

    // phase 1: scores (pair-batched, one sync per 2 l)
    ldQV(g_q);
    {
        const int ip1 = wid & 7;
        const int jh1 = (wid >> 3) * 32;
        const int dg  = (lane >> 4) * 16;
        const int jj  = jh1 + 2 * (lane & 15);
        float4 ra, rb;
        ldT(g_k, 0, ra); ldT(g_k, 1, rb);
        stT(ST, ra); stT(ST + KTSLOT, rb);
        for (int p = 0; p < 32; p++) {
            __syncthreads();
            if (p < 31) { ldT(g_k, 2*p + 2, ra); ldT(g_k, 2*p + 3, rb); }
            const float* kt0 = ST + (2 * (p & 1)) * KTSLOT;
            const float* kt1 = kt0 + KTSLOT;
            const float* q0 = &QV[((2*p) * 8 + ip1) * 32 + dg];
            const float* q1 = q0 + 256;
            float2 a0 = make_float2(0.f, 0.f), b0 = a0, a1 = a0, b1 = a0;
            #pragma unroll
            for (int d4 = 0; d4 < 16; d4 += 4) {
                float4 qa = *(const float4*)&q0[d4];
                float4 qb = *(const float4*)&q1[d4];
                fma2(a0, dup2(qa.x), *(const float2*)&kt0[(dg+d4+0)*KTSTRIDE + jj]);
                fma2(b0, dup2(qa.y), *(const float2*)&kt0[(dg+d4+1)*KTSTRIDE + jj]);
                fma2(a0, dup2(qa.z), *(const float2*)&kt0[(dg+d4+2)*KTSTRIDE + jj]);
                fma2(b0, dup2(qa.w), *(const float2*)&kt0[(dg+d4+3)*KTSTRIDE + jj]);
                fma2(a1, dup2(qb.x), *(const float2*)&kt1[(dg+d4+0)*KTSTRIDE + jj]);
                fma2(b1, dup2(qb.y), *(const float2*)&kt1[(dg+d4+1)*KTSTRIDE + jj]);
                fma2(a1, dup2(qb.z), *(const float2*)&kt1[(dg+d4+2)*KTSTRIDE + jj]);
                fma2(b1, dup2(qb.w), *(const float2*)&kt1[(dg+d4+3)*KTSTRIDE + jj]);
            }
            float sx0 = a0.x + b0.x, sy0 = a0.y + b0.y;
            float sx1 = a1.x + b1.x, sy1 = a1.y + b1.y;
            sx0 += __shfl_xor_sync(0xffffffffu, sx0, 16);
            sy0 += __shfl_xor_sync(0xffffffffu, sy0, 16);
            sx1 += __shfl_xor_sync(0xffffffffu, sx1, 16);
            sy1 += __shfl_xor_sync(0xffffffffu, sy1, 16);
            if (dg == 0) {
                *(float2*)&S[(2*p) * 512 + ip1 * 64 + jj] = make_float2(sx0 * SC, sy0 * SC);
                *(float2*)&S[(2*p+1) * 512 + ip1 * 64 + jj] = make_float2(sx1 * SC, sy1 * SC);
            }
            if (p < 31) {
                float* d0 = ST + (2 * ((p + 1) & 1)) * KTSLOT;
                stT(d0, ra); stT(d0 + KTSLOT, rb);
            }
        }
    }
    __syncthreads();

    // phase 2: v1 prefetch + softmax over l
    ldQV(g_v1);
    {
        const int col = tid;
        float r[64];
        float m0 = -1e30f, m1 = -1e30f;
        #pragma unroll
        for (int l = 0; l < 64; l += 2) {
            r[l] = S[l * 512 + col]; r[l+1] = S[(l+1) * 512 + col];
            m0 = fmaxf(m0, r[l]); m1 = fmaxf(m1, r[l+1]);
        }
        const float mx = fmaxf(m0, m1);
        float sA = 0.f, sB = 0.f;
        #pragma unroll
        for (int l = 0; l < 64; l += 2) {
            r[l] = __expf(r[l] - mx); sA += r[l];
            r[l+1] = __expf(r[l+1] - mx); sB += r[l+1];
        }
        const float inv = 1.f / (sA + sB);
        #pragma unroll
        for (int l = 0; l < 64; l++) S[l * 512 + col] = r[l] * inv;
    }
    __syncthreads();

    // phase 3: aggregate
    const int ipp = (wid & 3) * 2;
    const int jq  = (wid >> 2) * 16;
    auto issueV = [&](int l, int s) {
        const float* src = &g_v2[((size_t)((b * NN + l) * NN + sj0)) * EE + h * DD + sc0];
        cpasync16(st_u + 4u * (uint32_t)(s * VSLOT + sj0 * VTSTRIDE + sc0), src);
    };

    float2 acc0[8], acc1[8];
    #pragma unroll
    for (int p = 0; p < 8; p++) { acc0[p] = make_float2(0.f, 0.f); acc1[p] = make_float2(0.f, 0.f); }

    issueV(0, 0); CP_COMMIT;
    for (int l = 0; l < 64; l++) {
        if (l < 63) { issueV(l + 1, (l + 1) & 1); CP_COMMIT; CP_WAIT1; }
        else        { CP_WAIT0; }
        __syncthreads();
        const float* vt = ST + (l & 1) * VSLOT;
        const float2 v1a = dup2(QV[(l * 8 + ipp) * 32 + lane]);
        const float2 v1b = dup2(QV[(l * 8 + ipp + 1) * 32 + lane]);
        const float* a0 = &S[l * 512 + ipp * 64 + jq];
        const float* a1 = a0 + 64;
        #pragma unroll
        for (int g = 0; g < 4; g++) {
            const int j0 = jq + g * 4;
            float4 av0 = *(const float4*)&a0[g * 4];
            float4 av1 = *(const float4*)&a1[g * 4];
            float2 w0 = make_float2(vt[(j0+0)*VTSTRIDE + lane], vt[(j0+1)*VTSTRIDE + lane]);
            float2 w1 = make_float2(vt[(j0+2)*VTSTRIDE + lane], vt[(j0+3)*VTSTRIDE + lane]);
            float2 p0, p1, p2, p3;
            mul2(p0, make_float2(av0.x, av0.y), v1a);
            mul2(p1, make_float2(av0.z, av0.w), v1a);
            mul2(p2, make_float2(av1.x, av1.y), v1b);
            mul2(p3, make_float2(av1.z, av1.w), v1b);
            fma2(acc0[2*g],   p0, w0);
            fma2(acc0[2*g+1], p1, w1);
            fma2(acc1[2*g],   p2, w0);
            fma2(acc1[2*g+1], p3, w1);
        }
        __syncthreads();
    }

    #pragma unroll
    for (int ipx = 0; ipx < 2; ipx++) {
        const float2* ac = ipx ? acc1 : acc0;
        const size_t rowBase = ((size_t)(b * NN + iBase + ipp + ipx)) * NN;
        #pragma unroll
        for (int p = 0; p < 8; p++) {
            #pragma unroll
            for (int e = 0; e < 2; e++) {
                const int j = jq + 2 * p + e;
                const float val = e ? ac[p].y : ac[p].x;
                __nv_bfloat16 bh_, bl_; bfsplit(val, bh_, bl_);
                g_ao2[(rowBase + j) * 512 + h * DD + lane] = bh_;
                g_ao2[(rowBase + j) * 512 + 256 + h * DD + lane] = bl_;
            }
        }
    }
}

// =====================================================================
extern "C" void kernel_launch(void* const* d_in, const int* in_sizes, int n_in,
                              void* d_out, int out_size) {
    const float* x    = (const float*)d_in[0];
    const float* Wq   = (const float*)d_in[1];
    const float* Wk   = (const float*)d_in[2];
    const float* Wv1  = (const float*)d_in[3];
    const float* Wv2  = (const float*)d_in[4];
    const float* Wo   = (const float*)d_in[5];
    const float* lag  = (const float*)d_in[6];
    const float* lab  = (const float*)d_in[7];
    const float* W1   = (const float*)d_in[8];
    const float* b1   = (const float*)d_in[9];
    const float* W2   = (const float*)d_in[10];
    const float* b2   = (const float*)d_in[11];
    const float* log_ = (const float*)d_in[12];
    const float* lob  = (const float*)d_in[13];

    float *pq, *pk, *pv1, *pv2, *ph;
    __nv_bfloat16 *px2, *pao2, *ph2, *pm12, *pwqkv, *pwot, *pw1t, *pw2t;
    cudaGetSymbolAddress((void**)&pq,  g_q);
    cudaGetSymbolAddress((void**)&pk,  g_k);
    cudaGetSymbolAddress((void**)&pv1, g_v1);
    cudaGetSymbolAddress((void**)&pv2, g_v2);
    cudaGetSymbolAddress((void**)&ph,  g_h);
    cudaGetSymbolAddress((void**)&px2, g_x2);
    cudaGetSymbolAddress((void**)&pao2, g_ao2);
    cudaGetSymbolAddress((void**)&ph2, g_h2);
    cudaGetSymbolAddress((void**)&pm12, g_m12);
    cudaGetSymbolAddress((void**)&pwqkv, g_wqkv2);
    cudaGetSymbolAddress((void**)&pwot, g_wot2);
    cudaGetSymbolAddress((void**)&pw1t, g_w1t2);
    cudaGetSymbolAddress((void**)&pw2t, g_w2t2);

    // smem: BM=128/BN=128 stage=24576B x4 = 98304; BM=64/BN=256 stage=30720B x4 = 122880
    cudaFuncSetAttribute(gemm_mma<128,128,256,0,2>, cudaFuncAttributeMaxDynamicSharedMemorySize, 98304);
    cudaFuncSetAttribute(gemm_mma<128,128,256,1,2>, cudaFuncAttributeMaxDynamicSharedMemorySize, 98304);
    cudaFuncSetAttribute(gemm_mma<64,256,256,2,1>,  cudaFuncAttributeMaxDynamicSharedMemorySize, 122880);
    cudaFuncSetAttribute(gemm_mma<64,256,512,3,1>,  cudaFuncAttributeMaxDynamicSharedMemorySize, 122880);
    cudaFuncSetAttribute(attn_fused, cudaFuncAttributeMaxDynamicSharedMemorySize, ATTN_SMEM);

    // slot = 2 + launch index; QKV gemm at capture slot 6
    prep_all<<<1088, 256>>>(x, Wq, Wk, Wv1, Wv2, Wo, W1, W2);
    nop_k<<<1, 32>>>();
    nop_k<<<1, 32>>>();
    gemm_mma<128,128,256,0,2><<<dim3(64, 8), 256, 98304>>>(px2, pwqkv,
        nullptr, nullptr, nullptr, nullptr, pq, pk, pv1, pv2);
    attn_fused<<<128, 512, ATTN_SMEM>>>();
    gemm_mma<64,256,256,2,1><<<dim3(128, 1), 256, 122880>>>(pao2, pwot,
        x, nullptr, lag, lab, ph, ph2, nullptr, nullptr);
    gemm_mma<128,128,256,1,2><<<dim3(64, 4), 256, 98304>>>(ph2, pw1t,
        nullptr, b1, nullptr, nullptr, nullptr, pm12, nullptr, nullptr);
    gemm_mma<64,256,512,3,1><<<dim3(128, 1), 256, 122880>>>(pm12, pw2t,
        ph, b2, log_, lob, (float*)d_out, nullptr, nullptr, nullptr);
}

// round 15
// speedup vs baseline: 1.0909x; 1.0909x over previous
#include <cuda_runtime.h>
#include <cuda_bf16.h>
#include <math.h>
#include <stdint.h>

#define BB 2
#define NN 64
#define EE 256
#define HH 8
#define DD 32
#define FF 512
#define MR 8192
#define LNEPS 1e-5f

// ---------------- scratch ----------------
__device__ float g_q [MR*EE];
__device__ float g_k [MR*EE];
__device__ float g_v1[MR*EE];
__device__ float g_v2[MR*EE];
__device__ float g_h [MR*EE];
__device__ __nv_bfloat16 g_x2 [MR*512];
__device__ __nv_bfloat16 g_ao2[MR*512];
__device__ __nv_bfloat16 g_h2 [MR*512];
__device__ __nv_bfloat16 g_m12[(size_t)MR*1024];
__device__ __nv_bfloat16 g_wqkv2[1024*512];
__device__ __nv_bfloat16 g_wot2 [256*512];
__device__ __nv_bfloat16 g_w1t2 [512*512];
__device__ __nv_bfloat16 g_w2t2 [256*1024];

// ---------------- helpers ----------------
__device__ __forceinline__ uint32_t s2u(const void* p) {
    uint32_t a;
    asm("{ .reg .u64 t; cvta.to.shared.u64 t, %1; cvt.u32.u64 %0, t; }" : "=r"(a) : "l"(p));
    return a;
}
__device__ __forceinline__ void ldsm4(uint32_t* r, uint32_t a) {
    asm volatile("ldmatrix.sync.aligned.m8n8.x4.shared.b16 {%0,%1,%2,%3}, [%4];"
        : "=r"(r[0]), "=r"(r[1]), "=r"(r[2]), "=r"(r[3]) : "r"(a));
}
__device__ __forceinline__ void mma16816(float* c, const uint32_t* a, const uint32_t* b) {
    asm volatile("mma.sync.aligned.m16n8k16.row.col.f32.bf16.bf16.f32 "
        "{%0,%1,%2,%3}, {%4,%5,%6,%7}, {%8,%9}, {%0,%1,%2,%3};"
        : "+f"(c[0]), "+f"(c[1]), "+f"(c[2]), "+f"(c[3])
        : "r"(a[0]), "r"(a[1]), "r"(a[2]), "r"(a[3]), "r"(b[0]), "r"(b[1]));
}
__device__ __forceinline__ void bfsplit(float v, __nv_bfloat16& h, __nv_bfloat16& l) {
    h = __float2bfloat16_rn(v);
    l = __float2bfloat16_rn(v - __bfloat162float(h));
}
__device__ __forceinline__ void fma2(float2& c, const float2 a, const float2 b) {
    asm("fma.rn.f32x2 %0, %1, %2, %0;"
        : "+l"(reinterpret_cast<unsigned long long&>(c))
        : "l"(reinterpret_cast<const unsigned long long&>(a)),
          "l"(reinterpret_cast<const unsigned long long&>(b)));
}
__device__ __forceinline__ void mul2(float2& c, const float2 a, const float2 b) {
    asm("mul.rn.f32x2 %0, %1, %2;"
        : "=l"(reinterpret_cast<unsigned long long&>(c))
        : "l"(reinterpret_cast<const unsigned long long&>(a)),
          "l"(reinterpret_cast<const unsigned long long&>(b)));
}
__device__ __forceinline__ float2 dup2(float x) { float2 r; r.x = x; r.y = x; return r; }
__device__ __forceinline__ void cpasync16(uint32_t dst, const void* src) {
    asm volatile("cp.async.cg.shared.global [%0], [%1], 16;" :: "r"(dst), "l"(src) : "memory");
}
#define CP_COMMIT asm volatile("cp.async.commit_group;" ::: "memory")
#define CP_WAIT1  asm volatile("cp.async.wait_group 1;" ::: "memory")
#define CP_WAIT0  asm volatile("cp.async.wait_group 0;" ::: "memory")

// =====================================================================
// prep_all (unchanged, passing)
// =====================================================================
__global__ void __launch_bounds__(256)
prep_all(const float* __restrict__ x,
         const float* __restrict__ Wq, const float* __restrict__ Wk,
         const float* __restrict__ Wv1, const float* __restrict__ Wv2,
         const float* __restrict__ Wo, const float* __restrict__ W1,
         const float* __restrict__ W2)
{
    const int blk = blockIdx.x, tid = threadIdx.x;
    if (blk < 512) {
        const int base = blk * 4096;
        #pragma unroll
        for (int i = 0; i < 16; i++) {
            int t = base + i * 256 + tid;
            int row = t >> 8, c = t & 255;
            float v = x[t];
            __nv_bfloat16 h, l; bfsplit(v, h, l);
            g_x2[(size_t)row * 512 + c] = h;
            g_x2[(size_t)row * 512 + 256 + c] = l;
        }
        return;
    }
    __shared__ float tile[32][33];
    const int wb = blk - 512;
    const float* W; __nv_bfloat16* out; int K, N, tr, tc;
    if (wb < 256) {
        const int w = wb >> 6, t6 = wb & 63;
        W = (w == 0) ? Wq : (w == 1) ? Wk : (w == 2) ? Wv1 : Wv2;
        out = g_wqkv2 + w * 256 * 512; K = 256; N = 256; tr = t6 >> 3; tc = t6 & 7;
    } else if (wb < 320) {
        const int t6 = wb - 256;
        W = Wo; out = g_wot2; K = 256; N = 256; tr = t6 >> 3; tc = t6 & 7;
    } else if (wb < 448) {
        const int t6 = wb - 320;
        W = W1; out = g_w1t2; K = 256; N = 512; tr = t6 >> 4; tc = t6 & 15;
    } else {
        const int t6 = wb - 448;
        W = W2; out = g_w2t2; K = 512; N = 256; tr = t6 >> 3; tc = t6 & 7;
    }
    const int k0 = tr * 32, n0 = tc * 32;
    const int r = tid >> 3, c4 = (tid & 7) * 4;
    #pragma unroll
    for (int i = 0; i < 4; i++)
        tile[r][c4 + i] = W[(size_t)(k0 + r) * N + n0 + c4 + i];
    __syncthreads();
    #pragma unroll
    for (int i = 0; i < 4; i++) {
        float v = tile[c4 + i][r];
        __nv_bfloat16 h, l; bfsplit(v, h, l);
        out[(size_t)(n0 + r) * 2 * K + k0 + c4 + i] = h;
        out[(size_t)(n0 + r) * 2 * K + K + k0 + c4 + i] = l;
    }
}

// =====================================================================
// bf16 split-precision mma.sync GEMM (R13-measured-best version:
// 2-stage cp.async, K-chunk 32, row stride 40, MINB for BM=128 -> 2).
// =====================================================================
template<int BM, int BN, int KDIM, int MODE, int MINB>
__global__ void __launch_bounds__(256, MINB)
gemm_mma(const __nv_bfloat16* __restrict__ A2, const __nv_bfloat16* __restrict__ B2,
         const float* __restrict__ res, const float* __restrict__ bias,
         const float* __restrict__ lg, const float* __restrict__ lb,
         float* __restrict__ o0, void* __restrict__ o1v,
         float* __restrict__ o2, float* __restrict__ o3)
{
    constexpr int K2 = 2 * KDIM, C = KDIM / 32;
    constexpr int WR = BM / 32;
    constexpr int AH = 0, AL = BM * 40, BH = 2 * BM * 40, BL = 2 * BM * 40 + BN * 40;
    constexpr int SB = 2 * BM * 40 + 2 * BN * 40;
    extern __shared__ __nv_bfloat16 sm[];
    const int tid = threadIdx.x, wid = tid >> 5, lane = tid & 31;
    const int mBase = blockIdx.x * BM, nBase = blockIdx.y * BN;
    const int wrB = (wid % WR) * 32, wcB = (wid / WR) * 64;
    const uint32_t smu = s2u(sm);

    float acc[2][8][4];
    #pragma unroll
    for (int i = 0; i < 2; i++)
        #pragma unroll
        for (int j = 0; j < 8; j++)
            #pragma unroll
            for (int v = 0; v < 4; v++) acc[i][j][v] = 0.f;

    const int aRow = lane & 15, aK = ((lane >> 4) & 1) * 8;
    const int bN = ((lane >> 4) & 1) * 8 + (lane & 7), bK = ((lane >> 3) & 1) * 8;

    auto issue = [&](int c, int s) {
        const int ca = c * 32;
        const uint32_t base = smu + 2u * (uint32_t)(s * SB);
        #pragma unroll
        for (int i = 0; i < BM * 4 / 256; i++) {
            int f = tid + 256 * i; int r = f >> 2, c8 = (f & 3) * 8;
            const __nv_bfloat16* src = &A2[(size_t)(mBase + r) * K2 + ca + c8];
            cpasync16(base + 2u * (AH + r * 40 + c8), src);
            cpasync16(base + 2u * (AL + r * 40 + c8), src + KDIM);
        }
        #pragma unroll
        for (int i = 0; i < BN * 4 / 256; i++) {
            int f = tid + 256 * i; int r = f >> 2, c8 = (f & 3) * 8;
            const __nv_bfloat16* src = &B2[(size_t)(nBase + r) * K2 + ca + c8];
            cpasync16(base + 2u * (BH + r * 40 + c8), src);
            cpasync16(base + 2u * (BL + r * 40 + c8), src + KDIM);
        }
    };

    issue(0, 0); CP_COMMIT;
    for (int c = 0; c < C; c++) {
        const int s = c & 1;
        if (c + 1 < C) { issue(c + 1, s ^ 1); CP_COMMIT; CP_WAIT1; }
        else           { CP_WAIT0; }
        __syncthreads();
        const uint32_t sb = smu + 2u * (uint32_t)(s * SB);
        #pragma unroll
        for (int k16 = 0; k16 < 2; k16++) {
            const int k0 = k16 * 16;
            uint32_t ah[2][4], al_[2][4], bh[8][2], bl_[8][2];
            #pragma unroll
            for (int mr = 0; mr < 2; mr++) {
                ldsm4(ah[mr],  sb + 2u * (AH + (wrB + mr * 16 + aRow) * 40 + k0 + aK));
                ldsm4(al_[mr], sb + 2u * (AL + (wrB + mr * 16 + aRow) * 40 + k0 + aK));
            }
            #pragma unroll
            for (int np = 0; np < 4; np++) {
                uint32_t r4[4];
                ldsm4(r4, sb + 2u * (BH + (wcB + np * 16 + bN) * 40 + k0 + bK));
                bh[2*np][0] = r4[0]; bh[2*np][1] = r4[1];
                bh[2*np+1][0] = r4[2]; bh[2*np+1][1] = r4[3];
                ldsm4(r4, sb + 2u * (BL + (wcB + np * 16 + bN) * 40 + k0 + bK));
                bl_[2*np][0] = r4[0]; bl_[2*np][1] = r4[1];
                bl_[2*np+1][0] = r4[2]; bl_[2*np+1][1] = r4[3];
            }
            #pragma unroll
            for (int mr = 0; mr < 2; mr++)
                #pragma unroll
                for (int nc = 0; nc < 8; nc++) mma16816(acc[mr][nc], ah[mr], bh[nc]);
            #pragma unroll
            for (int mr = 0; mr < 2; mr++)
                #pragma unroll
                for (int nc = 0; nc < 8; nc++) mma16816(acc[mr][nc], ah[mr], bl_[nc]);
            #pragma unroll
            for (int mr = 0; mr < 2; mr++)
                #pragma unroll
                for (int nc = 0; nc < 8; nc++) mma16816(acc[mr][nc], al_[mr], bh[nc]);
        }
        __syncthreads();
    }

    const int lR = lane >> 2, lC = (lane & 3) * 2;
    if constexpr (MODE == 0) {
        const int sel = blockIdx.y >> 1;
        float* qout = sel == 0 ? o0 : sel == 1 ? (float*)o1v : sel == 2 ? o2 : o3;
        const int colBase = (blockIdx.y & 1) * 128 + wcB;
        #pragma unroll
        for (int mr = 0; mr < 2; mr++)
            #pragma unroll
            for (int nc = 0; nc < 8; nc++) {
                int row = mBase + wrB + mr * 16 + lR;
                int col = colBase + nc * 8 + lC;
                *(float2*)&qout[(size_t)row * 256 + col] = make_float2(acc[mr][nc][0], acc[mr][nc][1]);
                *(float2*)&qout[(size_t)(row + 8) * 256 + col] = make_float2(acc[mr][nc][2], acc[mr][nc][3]);
            }
    } else if constexpr (MODE == 1) {
        __nv_bfloat16* out = (__nv_bfloat16*)o1v;
        #pragma unroll
        for (int mr = 0; mr < 2; mr++)
            #pragma unroll
            for (int nc = 0; nc < 8; nc++) {
                int row = mBase + wrB + mr * 16 + lR;
                int colG = nBase + wcB + nc * 8 + lC;
                float b0 = bias[colG], b1 = bias[colG + 1];
                #pragma unroll
                for (int s = 0; s < 2; s++) {
                    int rr = row + s * 8;
                    float v0 = fmaxf(acc[mr][nc][2*s] + b0, 0.f);
                    float v1 = fmaxf(acc[mr][nc][2*s+1] + b1, 0.f);
                    __nv_bfloat162 hv, lv;
                    bfsplit(v0, hv.x, lv.x); bfsplit(v1, hv.y, lv.y);
                    *(__nv_bfloat162*)&out[(size_t)rr * 1024 + colG] = hv;
                    *(__nv_bfloat162*)&out[(size_t)rr * 1024 + 512 + colG] = lv;
                }
            }
    } else {
        float* stage = (float*)sm;   // [64][264]
        #pragma unroll
        for (int mr = 0; mr < 2; mr++)
            #pragma unroll
            for (int nc = 0; nc < 8; nc++) {
                int rowL = wrB + mr * 16 + lR;
                int col = wcB + nc * 8 + lC;
                *(float2*)&stage[rowL * 264 + col] = make_float2(acc[mr][nc][0], acc[mr][nc][1]);
                *(float2*)&stage[(rowL + 8) * 264 + col] = make_float2(acc[mr][nc][2], acc[mr][nc][3]);
            }
        __syncthreads();
        const int r = tid >> 2, q = tid & 3;
        const size_t grow = mBase + r;
        float sum = 0.f, sq = 0.f;
        #pragma unroll
        for (int c4 = 0; c4 < 16; c4++) {
            int cc = q * 64 + c4 * 4;
            float4 v = *(float4*)&stage[r * 264 + cc];
            float4 rv = *(const float4*)&res[grow * 256 + cc];
            v.x += rv.x; v.y += rv.y; v.z += rv.z; v.w += rv.w;
            if constexpr (MODE == 3) {
                float4 bv = *(const float4*)&bias[cc];
                v.x += bv.x; v.y += bv.y; v.z += bv.z; v.w += bv.w;
            }
            *(float4*)&stage[r * 264 + cc] = v;
            sum += v.x + v.y + v.z + v.w;
            sq  += v.x * v.x + v.y * v.y + v.z * v.z + v.w * v.w;
        }
        sum += __shfl_xor_sync(0xffffffffu, sum, 1);
        sum += __shfl_xor_sync(0xffffffffu, sum, 2);
        sq  += __shfl_xor_sync(0xffffffffu, sq, 1);
        sq  += __shfl_xor_sync(0xffffffffu, sq, 2);
        const float mean = sum * (1.f / 256.f);
        const float var  = sq * (1.f / 256.f) - mean * mean;
        const float rs   = rsqrtf(var + LNEPS);
        __nv_bfloat16* h2o = (__nv_bfloat16*)o1v;
        #pragma unroll
        for (int c4 = 0; c4 < 16; c4++) {
            int cc = q * 64 + c4 * 4;
            float4 v = *(float4*)&stage[r * 264 + cc];
            float4 g4 = *(const float4*)&lg[cc];
            float4 b4 = *(const float4*)&lb[cc];
            float4 y;
            y.x = (v.x - mean) * rs * g4.x + b4.x;
            y.y = (v.y - mean) * rs * g4.y + b4.y;
            y.z = (v.z - mean) * rs * g4.z + b4.z;
            y.w = (v.w - mean) * rs * g4.w + b4.w;
            *(float4*)&o0[grow * 256 + cc] = y;
            if constexpr (MODE == 2) {
                __nv_bfloat162 h01, l01, h23, l23;
                bfsplit(y.x, h01.x, l01.x); bfsplit(y.y, h01.y, l01.y);
                bfsplit(y.z, h23.x, l23.x); bfsplit(y.w, h23.y, l23.y);
                *(__nv_bfloat162*)&h2o[grow * 512 + cc]       = h01;
                *(__nv_bfloat162*)&h2o[grow * 512 + cc + 2]   = h23;
                *(__nv_bfloat162*)&h2o[grow * 512 + 256 + cc]     = l01;
                *(__nv_bfloat162*)&h2o[grow * 512 + 256 + cc + 2] = l23;
            }
        }
    }
}

// =====================================================================
// Fused attention v5 (unchanged from R13, passing)
// =====================================================================
#define SM_S   0
#define SM_QV  32768
#define SM_ST  49152
#define KTSLOT 2112
#define VSLOT  2560
#define KTSTRIDE 66
#define VTSTRIDE 40
#define ATTN_SMEM ((49152 + 4 * 2112) * 4)

__global__ void __launch_bounds__(512, 1)
attn_fused() {
    extern __shared__ float smf[];
    float* S  = smf + SM_S;
    float* QV = smf + SM_QV;
    float* ST = smf + SM_ST;
    const int bid = blockIdx.x;
    const int it = bid & 7, h = (bid >> 3) & 7, b = bid >> 6;
    const int iBase = it * 8;
    const int tid = threadIdx.x, wid = tid >> 5, lane = tid & 31;
    const float SC = 0.17677669529663687f;
    const uint32_t st_u = s2u(ST);

    const int sj0 = tid >> 3, sc0 = (tid & 7) * 4;
    auto ldT = [&](const float* __restrict__ src, int l, float4& r0) {
        r0 = *(const float4*)&src[((size_t)((b * NN + l) * NN + sj0)) * EE + h * DD + sc0];
    };
    auto stT = [&](float* kt, float4 r0) {
        kt[(sc0+0)*KTSTRIDE + sj0] = r0.x; kt[(sc0+1)*KTSTRIDE + sj0] = r0.y;
        kt[(sc0+2)*KTSTRIDE + sj0] = r0.z; kt[(sc0+3)*KTSTRIDE + sj0] = r0.w;
    };
    auto ldQV = [&](const float* __restrict__ src) {
        #pragma unroll
        for (int k = 0; k < 8; k++) {
            int f = tid + 512 * k;
            int row = f >> 3, d4 = (f & 7) * 4;
            int l = row >> 3, ip = row & 7;
            float4 v = *(const float4*)&src[((size_t)((b*NN + iBase + ip)*NN + l))*EE + h*DD + d4];
            *(float4*)&QV[row * 32 + d4] = v;
        }
    };

    // phase 1: scores (pair-batched, one sync per 2 l)
    ldQV(g_q);
    {
        const int ip1 = wid & 7;
        const int jh1 = (wid >> 3) * 32;
        const int dg  = (lane >> 4) * 16;
        const int jj  = jh1 + 2 * (lane & 15);
        float4 ra, rb;
        ldT(g_k, 0, ra); ldT(g_k, 1, rb);
        stT(ST, ra); stT(ST + KTSLOT, rb);
        for (int p = 0; p < 32; p++) {
            __syncthreads();
            if (p < 31) { ldT(g_k, 2*p + 2, ra); ldT(g_k, 2*p + 3, rb); }
            const float* kt0 = ST + (2 * (p & 1)) * KTSLOT;
            const float* kt1 = kt0 + KTSLOT;
            const float* q0 = &QV[((2*p) * 8 + ip1) * 32 + dg];
            const float* q1 = q0 + 256;
            float2 a0 = make_float2(0.f, 0.f), b0 = a0, a1 = a0, b1 = a0;
            #pragma unroll
            for (int d4 = 0; d4 < 16; d4 += 4) {
                float4 qa = *(const float4*)&q0[d4];
                float4 qb = *(const float4*)&q1[d4];
                fma2(a0, dup2(qa.x), *(const float2*)&kt0[(dg+d4+0)*KTSTRIDE + jj]);
                fma2(b0, dup2(qa.y), *(const float2*)&kt0[(dg+d4+1)*KTSTRIDE + jj]);
                fma2(a0, dup2(qa.z), *(const float2*)&kt0[(dg+d4+2)*KTSTRIDE + jj]);
                fma2(b0, dup2(qa.w), *(const float2*)&kt0[(dg+d4+3)*KTSTRIDE + jj]);
                fma2(a1, dup2(qb.x), *(const float2*)&kt1[(dg+d4+0)*KTSTRIDE + jj]);
                fma2(b1, dup2(qb.y), *(const float2*)&kt1[(dg+d4+1)*KTSTRIDE + jj]);
                fma2(a1, dup2(qb.z), *(const float2*)&kt1[(dg+d4+2)*KTSTRIDE + jj]);
                fma2(b1, dup2(qb.w), *(const float2*)&kt1[(dg+d4+3)*KTSTRIDE + jj]);
            }
            float sx0 = a0.x + b0.x, sy0 = a0.y + b0.y;
            float sx1 = a1.x + b1.x, sy1 = a1.y + b1.y;
            sx0 += __shfl_xor_sync(0xffffffffu, sx0, 16);
            sy0 += __shfl_xor_sync(0xffffffffu, sy0, 16);
            sx1 += __shfl_xor_sync(0xffffffffu, sx1, 16);
            sy1 += __shfl_xor_sync(0xffffffffu, sy1, 16);
            if (dg == 0) {
                *(float2*)&S[(2*p) * 512 + ip1 * 64 + jj] = make_float2(sx0 * SC, sy0 * SC);
                *(float2*)&S[(2*p+1) * 512 + ip1 * 64 + jj] = make_float2(sx1 * SC, sy1 * SC);
            }
            if (p < 31) {
                float* d0 = ST + (2 * ((p + 1) & 1)) * KTSLOT;
                stT(d0, ra); stT(d0 + KTSLOT, rb);
            }
        }
    }
    __syncthreads();

    // phase 2: v1 prefetch + softmax over l
    ldQV(g_v1);
    {
        const int col = tid;
        float r[64];
        float m0 = -1e30f, m1 = -1e30f;
        #pragma unroll
        for (int l = 0; l < 64; l += 2) {
            r[l] = S[l * 512 + col]; r[l+1] = S[(l+1) * 512 + col];
            m0 = fmaxf(m0, r[l]); m1 = fmaxf(m1, r[l+1]);
        }
        const float mx = fmaxf(m0, m1);
        float sA = 0.f, sB = 0.f;
        #pragma unroll
        for (int l = 0; l < 64; l += 2) {
            r[l] = __expf(r[l] - mx); sA += r[l];
            r[l+1] = __expf(r[l+1] - mx); sB += r[l+1];
        }
        const float inv = 1.f / (sA + sB);
        #pragma unroll
        for (int l = 0; l < 64; l++) S[l * 512 + col] = r[l] * inv;
    }
    __syncthreads();

    // phase 3: aggregate
    const int ipp = (wid & 3) * 2;
    const int jq  = (wid >> 2) * 16;
    auto issueV = [&](int l, int s) {
        const float* src = &g_v2[((size_t)((b * NN + l) * NN + sj0)) * EE + h * DD + sc0];
        cpasync16(st_u + 4u * (uint32_t)(s * VSLOT + sj0 * VTSTRIDE + sc0), src);
    };

    float2 acc0[8], acc1[8];
    #pragma unroll
    for (int p = 0; p < 8; p++) { acc0[p] = make_float2(0.f, 0.f); acc1[p] = make_float2(0.f, 0.f); }

    issueV(0, 0); CP_COMMIT;
    for (int l = 0; l < 64; l++) {
        if (l < 63) { issueV(l + 1, (l + 1) & 1); CP_COMMIT; CP_WAIT1; }
        else        { CP_WAIT0; }
        __syncthreads();
        const float* vt = ST + (l & 1) * VSLOT;
        const float2 v1a = dup2(QV[(l * 8 + ipp) * 32 + lane]);
        const float2 v1b = dup2(QV[(l * 8 + ipp + 1) * 32 + lane]);
        const float* a0 = &S[l * 512 + ipp * 64 + jq];
        const float* a1 = a0 + 64;
        #pragma unroll
        for (int g = 0; g < 4; g++) {
            const int j0 = jq + g * 4;
            float4 av0 = *(const float4*)&a0[g * 4];
            float4 av1 = *(const float4*)&a1[g * 4];
            float2 w0 = make_float2(vt[(j0+0)*VTSTRIDE + lane], vt[(j0+1)*VTSTRIDE + lane]);
            float2 w1 = make_float2(vt[(j0+2)*VTSTRIDE + lane], vt[(j0+3)*VTSTRIDE + lane]);
            float2 p0, p1, p2, p3;
            mul2(p0, make_float2(av0.x, av0.y), v1a);
            mul2(p1, make_float2(av0.z, av0.w), v1a);
            mul2(p2, make_float2(av1.x, av1.y), v1b);
            mul2(p3, make_float2(av1.z, av1.w), v1b);
            fma2(acc0[2*g],   p0, w0);
            fma2(acc0[2*g+1], p1, w1);
            fma2(acc1[2*g],   p2, w0);
            fma2(acc1[2*g+1], p3, w1);
        }
        __syncthreads();
    }

    #pragma unroll
    for (int ipx = 0; ipx < 2; ipx++) {
        const float2* ac = ipx ? acc1 : acc0;
        const size_t rowBase = ((size_t)(b * NN + iBase + ipp + ipx)) * NN;
        #pragma unroll
        for (int p = 0; p < 8; p++) {
            #pragma unroll
            for (int e = 0; e < 2; e++) {
                const int j = jq + 2 * p + e;
                const float val = e ? ac[p].y : ac[p].x;
                __nv_bfloat16 bh_, bl_; bfsplit(val, bh_, bl_);
                g_ao2[(rowBase + j) * 512 + h * DD + lane] = bh_;
                g_ao2[(rowBase + j) * 512 + 256 + h * DD + lane] = bl_;
            }
        }
    }
}

// =====================================================================
extern "C" void kernel_launch(void* const* d_in, const int* in_sizes, int n_in,
                              void* d_out, int out_size) {
    const float* x    = (const float*)d_in[0];
    const float* Wq   = (const float*)d_in[1];
    const float* Wk   = (const float*)d_in[2];
    const float* Wv1  = (const float*)d_in[3];
    const float* Wv2  = (const float*)d_in[4];
    const float* Wo   = (const float*)d_in[5];
    const float* lag  = (const float*)d_in[6];
    const float* lab  = (const float*)d_in[7];
    const float* W1   = (const float*)d_in[8];
    const float* b1   = (const float*)d_in[9];
    const float* W2   = (const float*)d_in[10];
    const float* b2   = (const float*)d_in[11];
    const float* log_ = (const float*)d_in[12];
    const float* lob  = (const float*)d_in[13];

    float *pq, *pk, *pv1, *pv2, *ph;
    __nv_bfloat16 *px2, *pao2, *ph2, *pm12, *pwqkv, *pwot, *pw1t, *pw2t;
    cudaGetSymbolAddress((void**)&pq,  g_q);
    cudaGetSymbolAddress((void**)&pk,  g_k);
    cudaGetSymbolAddress((void**)&pv1, g_v1);
    cudaGetSymbolAddress((void**)&pv2, g_v2);
    cudaGetSymbolAddress((void**)&ph,  g_h);
    cudaGetSymbolAddress((void**)&px2, g_x2);
    cudaGetSymbolAddress((void**)&pao2, g_ao2);
    cudaGetSymbolAddress((void**)&ph2, g_h2);
    cudaGetSymbolAddress((void**)&pm12, g_m12);
    cudaGetSymbolAddress((void**)&pwqkv, g_wqkv2);
    cudaGetSymbolAddress((void**)&pwot, g_wot2);
    cudaGetSymbolAddress((void**)&pw1t, g_w1t2);
    cudaGetSymbolAddress((void**)&pw2t, g_w2t2);

    cudaFuncSetAttribute(gemm_mma<128,128,256,0,2>, cudaFuncAttributeMaxDynamicSharedMemorySize, 81920);
    cudaFuncSetAttribute(gemm_mma<128,128,256,1,2>, cudaFuncAttributeMaxDynamicSharedMemorySize, 81920);
    cudaFuncSetAttribute(gemm_mma<64,256,256,2,1>,  cudaFuncAttributeMaxDynamicSharedMemorySize, 102400);
    cudaFuncSetAttribute(gemm_mma<64,256,512,3,1>,  cudaFuncAttributeMaxDynamicSharedMemorySize, 102400);
    cudaFuncSetAttribute(attn_fused, cudaFuncAttributeMaxDynamicSharedMemorySize, ATTN_SMEM);

    // zero pads: slot = 2 + launch index, so Wo GEMM (MODE 2) lands at
    // ncu capture slot 6 — first profile of the 64x256 single-wave GEMM.
    prep_all<<<1088, 256>>>(x, Wq, Wk, Wv1, Wv2, Wo, W1, W2);
    gemm_mma<128,128,256,0,2><<<dim3(64, 8), 256, 81920>>>(px2, pwqkv,
        nullptr, nullptr, nullptr, nullptr, pq, pk, pv1, pv2);
    attn_fused<<<128, 512, ATTN_SMEM>>>();
    gemm_mma<64,256,256,2,1><<<dim3(128, 1), 256, 102400>>>(pao2, pwot,
        x, nullptr, lag, lab, ph, ph2, nullptr, nullptr);
    gemm_mma<128,128,256,1,2><<<dim3(64, 4), 256, 81920>>>(ph2, pw1t,
        nullptr, b1, nullptr, nullptr, nullptr, pm12, nullptr, nullptr);
    gemm_mma<64,256,512,3,1><<<dim3(128, 1), 256, 102400>>>(pm12, pw2t,
        ph, b2, log_, lob, (float*)d_out, nullptr, nullptr, nullptr);
}